// round 16
// baseline (speedup 1.0000x reference)
#include <cuda_runtime.h>
#include <cuda.h>
#include <cuda_fp16.h>
#include <math.h>
#include <stdint.h>

#define BATCH 4096
#define DDIM  1024
#define NSTAGE 3
#define STAGE  32768u
#define HDR    4096u
#define DYN_SMEM (HDR + NSTAGE * STAGE)   // 102400 -> 2 CTAs/SM

// ------------------------- device scratch (no cudaMalloc) -------------------
__device__ __half g_ws[73400320];     // [14*5][n=1024][k=1024]
__device__ __half g_wb[41943040];     // [4*5][n=1024][k=2048]
__device__ __half g_x[5][4194304];    // s0,s1,n0,n1,n2: [4096][1024]
__device__ float  g_mix[4194304];     // per-CTA mix accumulator (16MB, L2-resident)

// ------------------------------ PTX helpers ---------------------------------
__device__ __forceinline__ uint32_t smem_u32(const void* p) {
    uint32_t a;
    asm("{ .reg .u64 t; cvta.to.shared.u64 t, %1; cvt.u32.u64 %0, t; }"
        : "=r"(a) : "l"(p));
    return a;
}

#define MBAR_INIT(addr, cnt) \
    asm volatile("mbarrier.init.shared.b64 [%0], %1;" :: "r"(addr), "r"((uint32_t)(cnt)) : "memory")
#define MBAR_EXPECT_TX(addr, bytes) \
    asm volatile("mbarrier.arrive.expect_tx.shared.b64 _, [%0], %1;" :: "r"(addr), "r"((uint32_t)(bytes)) : "memory")
#define MBAR_ARRIVE(addr) \
    asm volatile("mbarrier.arrive.shared.b64 _, [%0];" :: "r"(addr) : "memory")
#define MBAR_WAIT(addr, ph) do {                                              \
    asm volatile(                                                             \
        "{\n\t.reg .pred P1;\n\t"                                             \
        "WL_%=:\n\t"                                                          \
        "mbarrier.try_wait.parity.acquire.cta.shared::cta.b64 P1, [%0], %1, 0x989680;\n\t" \
        "@P1 bra.uni WD_%=;\n\t"                                              \
        "bra.uni WL_%=;\n\t"                                                  \
        "WD_%=:\n\t}"                                                         \
        :: "r"((uint32_t)(addr)), "r"((uint32_t)(ph)) : "memory");            \
} while (0)

#define TMA2D(smaddr, map, cx, cy, mbar) \
    asm volatile("cp.async.bulk.tensor.2d.shared::cta.global.tile.mbarrier::complete_tx::bytes " \
                 "[%0], [%1, {%2, %3}], [%4];" \
                 :: "r"(smaddr), "l"(map), "r"(cx), "r"(cy), "r"(mbar) : "memory")

__device__ __forceinline__ void ldsm4(uint32_t addr, uint32_t r[4]) {
    asm volatile("ldmatrix.sync.aligned.m8n8.x4.shared.b16 {%0,%1,%2,%3}, [%4];"
        : "=r"(r[0]), "=r"(r[1]), "=r"(r[2]), "=r"(r[3]) : "r"(addr));
}

__device__ __forceinline__ void mma16816(float c[4], const uint32_t a[4],
                                         uint32_t b0, uint32_t b1) {
    asm volatile("mma.sync.aligned.m16n8k16.row.col.f32.f16.f16.f32 "
        "{%0,%1,%2,%3}, {%4,%5,%6,%7}, {%8,%9}, {%0,%1,%2,%3};"
        : "+f"(c[0]), "+f"(c[1]), "+f"(c[2]), "+f"(c[3])
        : "r"(a[0]), "r"(a[1]), "r"(a[2]), "r"(a[3]), "r"(b0), "r"(b1));
}

// single-MUFU tanh (sm_75+); sigmoid(h) = 0.5 + 0.5*tanh(h/2)
__device__ __forceinline__ float tanh_fast(float x) {
    float y;
    asm("tanh.approx.f32 %0, %1;" : "=f"(y) : "f"(x));
    return y;
}

// ------------------------------- structs ------------------------------------
struct EdgeInfo {
    int a0, a1;        // g_x index for k<1024 / k>=1024
    int b_is_wb;       // 0: g_ws, 1: g_wb
    int b_row_base;    // tensor-local row base (idx*5*1024)
    int K;             // 1024 or 2048
    int layer;         // global layer index
};
struct NodeP {
    CUtensorMap a_map[5];
    CUtensorMap ws_map, wb_map;
    EdgeInfo e[6];
    int n_edges;
    int node_out_idx;  // 2..4 -> g_x dest, -1 -> final fp32 out
};

// --------------------------- conversion kernels -----------------------------
__global__ void cvt_in2(const float* __restrict__ s0,
                        const float* __restrict__ s1) {
    const int i = (blockIdx.x * 256 + threadIdx.x) * 4;
    float4 v0 = *(const float4*)(s0 + i);
    float4 v1 = *(const float4*)(s1 + i);
    *(__half2*)&g_x[0][i]     = __floats2half2_rn(v0.x, v0.y);
    *(__half2*)&g_x[0][i + 2] = __floats2half2_rn(v0.z, v0.w);
    *(__half2*)&g_x[1][i]     = __floats2half2_rn(v1.x, v1.y);
    *(__half2*)&g_x[1][i + 2] = __floats2half2_rn(v1.z, v1.w);
}

__global__ void cvt_w2(const float* __restrict__ Ws,
                       const float* __restrict__ Wb) {
    __shared__ float t[32][33];
    const int z = blockIdx.z;
    const float* src; __half* dst; int K, zz;
    if (z < 70) { src = Ws; dst = g_ws; K = 1024; zz = z; }
    else        { src = Wb; dst = g_wb; K = 2048; zz = z - 70; }
    if ((int)blockIdx.x >= K / 32) return;
    const int k0 = blockIdx.x * 32, n0 = blockIdx.y * 32;
    const int tx = threadIdx.x, ty = threadIdx.y;   // (32, 8)
    const float* s = src + (size_t)zz * K * 1024;
    #pragma unroll
    for (int r = 0; r < 4; r++)
        t[ty + 8 * r][tx] = s[(size_t)(k0 + ty + 8 * r) * 1024 + n0 + tx];
    __syncthreads();
    const size_t dbase = (size_t)zz * 1024 * K;
    const int id = ty * 32 + tx;
    #pragma unroll
    for (int rep = 0; rep < 2; rep++) {
        const int idx = id + rep * 256;
        const int nl = idx >> 4, k2 = idx & 15;
        const __half2 v = __floats2half2_rn(t[2 * k2][nl], t[2 * k2 + 1][nl]);
        *(__half2*)&dst[dbase + (size_t)(n0 + nl) * K + k0 + 2 * k2] = v;
    }
}

// ------------------------------ GEMM kernel ---------------------------------
__global__ void __launch_bounds__(256, 2)
gemm_node(const __grid_constant__ NodeP P,
          const float* __restrict__ geno,
          const float* __restrict__ bsv,
          float* __restrict__ outp)
{
    extern __shared__ char dynsmem[];
    const uint32_t sb = smem_u32(dynsmem);
    const uint32_t tile0 = sb + HDR;
    float* sbias = (float*)(dynsmem + 512);     // [5][128]
    const int tid = (int)threadIdx.x;
    const int lane = tid & 31, wid = tid >> 5;
    const int bm = blockIdx.y * 128, bn = blockIdx.x * 128;
    const int mbase = (wid >> 2) * 64;   // 2 m-warps
    const int nbase = (wid & 3) * 32;    // 4 n-warps
    float* mixg = g_mix + ((size_t)(blockIdx.y * gridDim.x + blockIdx.x) * 16384);

    if (tid == 0) {
        #pragma unroll
        for (int s = 0; s < NSTAGE; s++) {
            MBAR_INIT(sb + s * 8, 1);          // full: tx-based
            MBAR_INIT(sb + 64 + s * 8, 8);     // empty: one arrive per warp
        }
    }
    __syncthreads();

    // per-thread ldmatrix row offsets (rows of 128B = 64 fp16)
    uint32_t aOff[4]; int aSw[4];
    #pragma unroll
    for (int mb = 0; mb < 4; mb++) {
        const int r = mbase + mb * 16 + (lane & 15);
        aOff[mb] = (uint32_t)r * 128u; aSw[mb] = r & 7;
    }
    uint32_t bOff[2]; int bSw[2];
    #pragma unroll
    for (int nb = 0; nb < 2; nb++) {
        const int r = nbase + nb * 16 + (lane & 7) + ((lane >> 3) & 1) * 8;
        bOff[nb] = (uint32_t)r * 128u; bSw[nb] = r & 7;
    }
    const int hi16 = lane >> 4;

    // producer iterator state (tid 0 only)
    int pe = 0, pop = 0, pkt = 0;

    auto issue = [&](int t) {
        if (pe >= P.n_edges) return;
        const EdgeInfo ei = P.e[pe];
        const int s = t % NSTAGE;
        if (t >= NSTAGE) {
            const int ph = ((t / NSTAGE) + 1) & 1;
            MBAR_WAIT(sb + 64 + s * 8, ph);
        }
        const uint32_t st = tile0 + (uint32_t)s * STAGE;
        MBAR_EXPECT_TX(sb + s * 8, STAGE);
        const int kg = pkt * 64;
        int ka = kg;
        const CUtensorMap* A = &P.a_map[ei.a0];
        if (kg >= 1024) { A = &P.a_map[ei.a1]; ka = kg - 1024; }
        const CUtensorMap* B = ei.b_is_wb ? &P.wb_map : &P.ws_map;
        const int by = ei.b_row_base + pop * 1024 + bn;
        TMA2D(st,           A, ka, bm, sb + s * 8);
        TMA2D(st + 16384u,  B, kg, by, sb + s * 8);
        if (++pkt == ei.K / 64) { pkt = 0; if (++pop == 5) { pop = 0; ++pe; } }
    };

    if (tid == 0) {
        #pragma unroll
        for (int s = 0; s < NSTAGE; s++) issue(s);
    }

    int t = 0;
    for (int e = 0; e < P.n_edges; e++) {
        const EdgeInfo ei = P.e[e];
        const int nch = ei.K / 64;

        // preload all 5 op biases for this edge (2 syncs per edge, not 10)
        __syncthreads();
        if (tid < 128) {
            #pragma unroll
            for (int i = 0; i < 5; i++)
                sbias[i * 128 + tid] =
                    __ldg(&bsv[((size_t)ei.layer * 5 + i) * 1024 + bn + tid]);
        }
        __syncthreads();
        float w5[5];
        #pragma unroll
        for (int i = 0; i < 5; i++) w5[i] = __ldg(&geno[ei.layer * 5 + i]);

        for (int op = 0; op < 5; op++) {
            float c[4][4][4];
            #pragma unroll
            for (int i = 0; i < 4; i++)
                #pragma unroll
                for (int j = 0; j < 4; j++)
                    #pragma unroll
                    for (int r = 0; r < 4; r++) c[i][j][r] = 0.0f;

            for (int kt = 0; kt < nch; kt++) {
                const int s = t % NSTAGE;
                MBAR_WAIT(sb + s * 8, (t / NSTAGE) & 1);
                const uint32_t st = tile0 + (uint32_t)s * STAGE;
                const uint32_t stB = st + 16384u;

                #pragma unroll
                for (int ks = 0; ks < 4; ks++) {
                    const int k2 = ks * 2 + hi16;
                    uint32_t bfrag[2][4], afrag[4][4];
                    #pragma unroll
                    for (int nb = 0; nb < 2; nb++)
                        ldsm4(stB + bOff[nb] + (uint32_t)((k2 ^ bSw[nb]) * 16),
                              bfrag[nb]);
                    #pragma unroll
                    for (int mb = 0; mb < 4; mb++)
                        ldsm4(st + aOff[mb] + (uint32_t)((k2 ^ aSw[mb]) * 16),
                              afrag[mb]);
                    #pragma unroll
                    for (int mb = 0; mb < 4; mb++)
                        #pragma unroll
                        for (int n8 = 0; n8 < 4; n8++) {
                            const int nb = n8 >> 1, hf = n8 & 1;
                            mma16816(c[mb][n8], afrag[mb],
                                     bfrag[nb][hf], bfrag[nb][hf + 2]);
                        }
                }
                if (lane == 0) MBAR_ARRIVE(sb + 64 + s * 8);
                if (tid == 0) issue(t + NSTAGE);
                t++;
            }

            // ------- epilogue: mixg (+)= geno * act(c + bias), float4 RMW ---
            const float wgt = w5[op];
            const float* sb_op = sbias + op * 128;
            const bool first = (e == 0) && (op == 0);
            const bool last  = (e == P.n_edges - 1) && (op == 4);

            #define MIX_BODY(AEXPR)                                            \
                _Pragma("unroll")                                              \
                for (int mb = 0; mb < 4; mb++)                                 \
                _Pragma("unroll")                                              \
                for (int n8 = 0; n8 < 4; n8++) {                               \
                    const int n0l = nbase + n8 * 8 + (lane & 3) * 2;           \
                    const float b0 = sb_op[n0l], b1 = sb_op[n0l + 1];          \
                    float vv[4];                                               \
                    _Pragma("unroll")                                          \
                    for (int r = 0; r < 4; r++) {                              \
                        const float h = c[mb][n8][r] + ((r & 1) ? b1 : b0);    \
                        vv[r] = wgt * (AEXPR);                                 \
                    }                                                          \
                    float4* mp = (float4*)&mixg[((mb * 4 + n8) * 256 + tid)    \
                                                * 4];                          \
                    if (first) {                                               \
                        *mp = make_float4(vv[0], vv[1], vv[2], vv[3]);         \
                    } else if (!last) {                                        \
                        float4 o = *mp;                                        \
                        o.x += vv[0]; o.y += vv[1];                            \
                        o.z += vv[2]; o.w += vv[3];                            \
                        *mp = o;                                               \
                    } else {                                                   \
                        float4 o = *mp;                                        \
                        const float t0 = o.x + vv[0], t1 = o.y + vv[1];        \
                        const float t2 = o.z + vv[2], t3 = o.w + vv[3];        \
                        const int m = bm + mbase + mb * 16 + (lane >> 2);      \
                        const int n = bn + n0l;                                \
                        if (P.node_out_idx >= 0) {                             \
                            __half* dh = g_x[P.node_out_idx];                  \
                            *(__half2*)&dh[(size_t)m * 1024 + n] =             \
                                __floats2half2_rn(t0, t1);                     \
                            *(__half2*)&dh[(size_t)(m + 8) * 1024 + n] =       \
                                __floats2half2_rn(t2, t3);                     \
                        } else {                                               \
                            *(float2*)&outp[(size_t)m * 1024 + n] =            \
                                make_float2(t0, t1);                           \
                            *(float2*)&outp[(size_t)(m + 8) * 1024 + n] =      \
                                make_float2(t2, t3);                           \
                        }                                                      \
                    }                                                          \
                }
            switch (op) {
                case 0: MIX_BODY(h); break;
                case 1: MIX_BODY(fmaxf(h, 0.0f)); break;
                case 2: MIX_BODY(tanh_fast(h)); break;
                case 3: MIX_BODY(fmaf(tanh_fast(0.5f * h), 0.5f, 0.5f)); break;
                default: MIX_BODY(h > 0.0f ? h : 0.2f * h); break;
            }
            #undef MIX_BODY
        }
    }
}

// --------------------------------- host -------------------------------------
typedef CUresult (*EncodeFn)(CUtensorMap*, CUtensorMapDataType, cuuint32_t, void*,
                             const cuuint64_t*, const cuuint64_t*, const cuuint32_t*,
                             const cuuint32_t*, CUtensorMapInterleave, CUtensorMapSwizzle,
                             CUtensorMapL2promotion, CUtensorMapFloatOOBfill);

static void make2d(EncodeFn enc, CUtensorMap* out, void* base,
                   uint64_t dim0, uint64_t dim1, uint64_t stride_b, uint32_t boxh) {
    cuuint64_t dims[2]    = {dim0, dim1};
    cuuint64_t strides[1] = {stride_b};
    cuuint32_t box[2]     = {64u, boxh};
    cuuint32_t es[2]      = {1u, 1u};
    enc(out, CU_TENSOR_MAP_DATA_TYPE_FLOAT16, 2, base, dims, strides, box, es,
        CU_TENSOR_MAP_INTERLEAVE_NONE, CU_TENSOR_MAP_SWIZZLE_128B,
        CU_TENSOR_MAP_L2_PROMOTION_L2_128B, CU_TENSOR_MAP_FLOAT_OOB_FILL_NONE);
}

extern "C" void kernel_launch(void* const* d_in, const int* in_sizes, int n_in,
                              void* d_out, int out_size)
{
    const float *s0 = nullptr, *s1 = nullptr, *geno = nullptr;
    const float *Ws = nullptr, *Wb = nullptr, *bsv = nullptr;
    for (int i = 0; i < n_in; i++) {
        const long sz = (long)in_sizes[i];
        const float* p = (const float*)d_in[i];
        if      (sz == (long)BATCH * DDIM)   { if (!s0) s0 = p; else s1 = p; }
        else if (sz == 90L)                    geno = p;
        else if (sz == 73400320L)              Ws = p;
        else if (sz == 41943040L)              Wb = p;
        else if (sz == 92160L)                 bsv = p;
    }

    void *ws, *wb, *x;
    cudaGetSymbolAddress(&ws, g_ws);
    cudaGetSymbolAddress(&wb, g_wb);
    cudaGetSymbolAddress(&x,  g_x);

    void* fp = nullptr;
    cudaDriverEntryPointQueryResult qres;
    cudaGetDriverEntryPointByVersion("cuTensorMapEncodeTiled", &fp, 12000,
                                     cudaEnableDefault, &qres);
    EncodeFn enc = (EncodeFn)fp;

    NodeP base;
    for (int i = 0; i < 5; i++)
        make2d(enc, &base.a_map[i], (char*)x + (size_t)i * 4194304 * 2, 1024, 4096, 2048, 128);
    make2d(enc, &base.ws_map, ws, 1024, 71680, 2048, 128);
    make2d(enc, &base.wb_map, wb, 2048, 20480, 4096, 128);

    cvt_in2<<<4096, 256>>>(s0, s1);
    dim3 tb(32, 8);
    cvt_w2<<<dim3(64, 32, 90), tb>>>(Ws, Wb);

    cudaFuncSetAttribute(gemm_node, cudaFuncAttributeMaxDynamicSharedMemorySize, DYN_SMEM);

    dim3 grid(8, 32), blk(256);
    int si = 0, bi = 0, offset = 0;
    for (int node = 0; node < 4; node++) {
        NodeP P = base;
        P.n_edges = node + 3;
        for (int j = 0; j < node + 3; j++) {
            EdgeInfo& e = P.e[j];
            e.layer = offset + j;
            if (j == 2) {
                e.b_is_wb = 1; e.b_row_base = bi * 5 * 1024; bi++;
                e.K = 2048; e.a0 = 0; e.a1 = 1;
            } else {
                e.b_is_wb = 0; e.b_row_base = si * 5 * 1024; si++;
                e.K = 1024;
                e.a0 = e.a1 = (j < 2) ? j : (j - 1);
            }
        }
        P.node_out_idx = (node < 3) ? (2 + node) : -1;
        gemm_node<<<grid, blk, DYN_SMEM>>>(P, geno, bsv, (float*)d_out);
        offset += node + 3;
    }
}

// round 17
// speedup vs baseline: 1.0380x; 1.0380x over previous
#include <cuda_runtime.h>
#include <cuda.h>
#include <cuda_fp16.h>
#include <math.h>
#include <stdint.h>

#define BATCH 4096
#define DDIM  1024
#define NSTAGE 3
#define STAGE  32768u
#define DYN_SMEM (2048u + NSTAGE * STAGE)   // 100352 bytes -> 2 CTAs/SM

// ------------------------- device scratch (no cudaMalloc) -------------------
__device__ __half g_ws[73400320];     // [14*5][n=1024][k=1024]
__device__ __half g_wb[41943040];     // [4*5][n=1024][k=2048]
__device__ __half g_x[5][4194304];    // s0,s1,n0,n1,n2: [4096][1024]
__device__ float  g_mix[4194304];     // per-CTA mix accumulator (16MB, L2-resident)

// ------------------------------ PTX helpers ---------------------------------
__device__ __forceinline__ uint32_t smem_u32(const void* p) {
    uint32_t a;
    asm("{ .reg .u64 t; cvta.to.shared.u64 t, %1; cvt.u32.u64 %0, t; }"
        : "=r"(a) : "l"(p));
    return a;
}

#define MBAR_INIT(addr, cnt) \
    asm volatile("mbarrier.init.shared.b64 [%0], %1;" :: "r"(addr), "r"((uint32_t)(cnt)) : "memory")
#define MBAR_EXPECT_TX(addr, bytes) \
    asm volatile("mbarrier.arrive.expect_tx.shared.b64 _, [%0], %1;" :: "r"(addr), "r"((uint32_t)(bytes)) : "memory")
#define MBAR_ARRIVE(addr) \
    asm volatile("mbarrier.arrive.shared.b64 _, [%0];" :: "r"(addr) : "memory")
#define MBAR_WAIT(addr, ph) do {                                              \
    asm volatile(                                                             \
        "{\n\t.reg .pred P1;\n\t"                                             \
        "WL_%=:\n\t"                                                          \
        "mbarrier.try_wait.parity.acquire.cta.shared::cta.b64 P1, [%0], %1, 0x989680;\n\t" \
        "@P1 bra.uni WD_%=;\n\t"                                              \
        "bra.uni WL_%=;\n\t"                                                  \
        "WD_%=:\n\t}"                                                         \
        :: "r"((uint32_t)(addr)), "r"((uint32_t)(ph)) : "memory");            \
} while (0)

#define TMA2D(smaddr, map, cx, cy, mbar) \
    asm volatile("cp.async.bulk.tensor.2d.shared::cta.global.tile.mbarrier::complete_tx::bytes " \
                 "[%0], [%1, {%2, %3}], [%4];" \
                 :: "r"(smaddr), "l"(map), "r"(cx), "r"(cy), "r"(mbar) : "memory")

__device__ __forceinline__ void ldsm4(uint32_t addr, uint32_t r[4]) {
    asm volatile("ldmatrix.sync.aligned.m8n8.x4.shared.b16 {%0,%1,%2,%3}, [%4];"
        : "=r"(r[0]), "=r"(r[1]), "=r"(r[2]), "=r"(r[3]) : "r"(addr));
}

__device__ __forceinline__ void mma16816(float c[4], const uint32_t a[4],
                                         uint32_t b0, uint32_t b1) {
    asm volatile("mma.sync.aligned.m16n8k16.row.col.f32.f16.f16.f32 "
        "{%0,%1,%2,%3}, {%4,%5,%6,%7}, {%8,%9}, {%0,%1,%2,%3};"
        : "+f"(c[0]), "+f"(c[1]), "+f"(c[2]), "+f"(c[3])
        : "r"(a[0]), "r"(a[1]), "r"(a[2]), "r"(a[3]), "r"(b0), "r"(b1));
}

// single-MUFU tanh (sm_75+); sigmoid(h) = 0.5 + 0.5*tanh(h/2)
__device__ __forceinline__ float tanh_fast(float x) {
    float y;
    asm("tanh.approx.f32 %0, %1;" : "=f"(y) : "f"(x));
    return y;
}

// ------------------------------- structs ------------------------------------
struct EdgeInfo {
    int a0, a1;        // g_x index for k<1024 / k>=1024
    int b_is_wb;       // 0: g_ws, 1: g_wb
    int b_row_base;    // tensor-local row base (idx*5*1024)
    int K;             // 1024 or 2048
    int layer;         // global layer index
};
struct NodeP {
    CUtensorMap a_map[5];
    CUtensorMap ws_map, wb_map;
    EdgeInfo e[6];
    int n_edges;
    int node_out_idx;  // 2..4 -> g_x dest, -1 -> final fp32 out
};

// --------------------------- conversion kernels -----------------------------
__global__ void cvt_in2(const float* __restrict__ s0,
                        const float* __restrict__ s1) {
    const int i = (blockIdx.x * 256 + threadIdx.x) * 4;
    float4 v0 = *(const float4*)(s0 + i);
    float4 v1 = *(const float4*)(s1 + i);
    *(__half2*)&g_x[0][i]     = __floats2half2_rn(v0.x, v0.y);
    *(__half2*)&g_x[0][i + 2] = __floats2half2_rn(v0.z, v0.w);
    *(__half2*)&g_x[1][i]     = __floats2half2_rn(v1.x, v1.y);
    *(__half2*)&g_x[1][i + 2] = __floats2half2_rn(v1.z, v1.w);
}

__global__ void cvt_w2(const float* __restrict__ Ws,
                       const float* __restrict__ Wb) {
    __shared__ float t[32][33];
    const int z = blockIdx.z;
    const float* src; __half* dst; int K, zz;
    if (z < 70) { src = Ws; dst = g_ws; K = 1024; zz = z; }
    else        { src = Wb; dst = g_wb; K = 2048; zz = z - 70; }
    if ((int)blockIdx.x >= K / 32) return;
    const int k0 = blockIdx.x * 32, n0 = blockIdx.y * 32;
    const int tx = threadIdx.x, ty = threadIdx.y;   // (32, 8)
    const float* s = src + (size_t)zz * K * 1024;
    #pragma unroll
    for (int r = 0; r < 4; r++)
        t[ty + 8 * r][tx] = s[(size_t)(k0 + ty + 8 * r) * 1024 + n0 + tx];
    __syncthreads();
    const size_t dbase = (size_t)zz * 1024 * K;
    const int id = ty * 32 + tx;
    #pragma unroll
    for (int rep = 0; rep < 2; rep++) {
        const int idx = id + rep * 256;
        const int nl = idx >> 4, k2 = idx & 15;
        const __half2 v = __floats2half2_rn(t[2 * k2][nl], t[2 * k2 + 1][nl]);
        *(__half2*)&dst[dbase + (size_t)(n0 + nl) * K + k0 + 2 * k2] = v;
    }
}

// ------------------------------ GEMM kernel ---------------------------------
// R15 structure; mainloop ALU stripped: all 24 ldsm stage-relative offsets
// precomputed into registers, and %/div stage tracking replaced by rotating
// counters (consumer cs/cph; producer ps/wph/wsr).
__global__ void __launch_bounds__(256, 2)
gemm_node(const __grid_constant__ NodeP P,
          const float* __restrict__ geno,
          const float* __restrict__ bsv,
          float* __restrict__ outp)
{
    extern __shared__ char dynsmem[];
    const uint32_t sb = smem_u32(dynsmem);
    const uint32_t tile0 = sb + 2048u;
    float* sbias = (float*)(dynsmem + 256);
    const int tid = (int)threadIdx.x;
    const int lane = tid & 31, wid = tid >> 5;
    const int bm = blockIdx.y * 128, bn = blockIdx.x * 128;
    const int mbase = (wid >> 2) * 64;   // 2 m-warps
    const int nbase = (wid & 3) * 32;    // 4 n-warps
    float* mixg = g_mix + ((size_t)(blockIdx.y * gridDim.x + blockIdx.x) * 16384);

    if (tid == 0) {
        #pragma unroll
        for (int s = 0; s < NSTAGE; s++) {
            MBAR_INIT(sb + s * 8, 1);          // full: tx-based
            MBAR_INIT(sb + 64 + s * 8, 8);     // empty: one arrive per warp
        }
    }
    __syncthreads();

    // ---- precomputed ldsm offsets (stage-relative), 24 registers ----
    const int hi16 = lane >> 4;
    uint32_t addrA[4][4];   // [ks][mb]
    uint32_t addrB[4][2];   // [ks][nb]  (includes +16384 B-region offset)
    #pragma unroll
    for (int mb = 0; mb < 4; mb++) {
        const int r = mbase + mb * 16 + (lane & 15);
        #pragma unroll
        for (int ks = 0; ks < 4; ks++)
            addrA[ks][mb] = (uint32_t)(r * 128) +
                (uint32_t)((((ks * 2 + hi16) ^ (r & 7)) * 16));
    }
    #pragma unroll
    for (int nb = 0; nb < 2; nb++) {
        const int r = nbase + nb * 16 + (lane & 7) + ((lane >> 3) & 1) * 8;
        #pragma unroll
        for (int ks = 0; ks < 4; ks++)
            addrB[ks][nb] = 16384u + (uint32_t)(r * 128) +
                (uint32_t)((((ks * 2 + hi16) ^ (r & 7)) * 16));
    }

    // producer iterator state (tid 0 only): rotating counters, no division
    int pe = 0, pop = 0, pkt = 0;
    int ps = 0, issTot = 0, wph = 0, wsr = 0;

    auto issue = [&]() {
        if (pe >= P.n_edges) return;
        const EdgeInfo ei = P.e[pe];
        if (issTot >= NSTAGE) {
            MBAR_WAIT(sb + 64 + ps * 8, wph);
            if (++wsr == NSTAGE) { wsr = 0; wph ^= 1; }
        }
        const uint32_t st = tile0 + (uint32_t)ps * STAGE;
        MBAR_EXPECT_TX(sb + ps * 8, STAGE);
        const int kg = pkt * 64;
        int ka = kg;
        const CUtensorMap* A = &P.a_map[ei.a0];
        if (kg >= 1024) { A = &P.a_map[ei.a1]; ka = kg - 1024; }
        const CUtensorMap* B = ei.b_is_wb ? &P.wb_map : &P.ws_map;
        const int by = ei.b_row_base + pop * 1024 + bn;
        TMA2D(st,           A, ka, bm, sb + ps * 8);
        TMA2D(st + 16384u,  B, kg, by, sb + ps * 8);
        issTot++;
        if (++ps == NSTAGE) ps = 0;
        if (++pkt == ei.K / 64) { pkt = 0; if (++pop == 5) { pop = 0; ++pe; } }
    };

    if (tid == 0) {
        #pragma unroll
        for (int s = 0; s < NSTAGE; s++) issue();
    }

    // consumer rotating state
    int cs = 0, cph = 0;

    for (int e = 0; e < P.n_edges; e++) {
        const int layer = P.e[e].layer;
        const int nch = P.e[e].K / 64;

        for (int op = 0; op < 5; op++) {
            float c[4][4][4];
            #pragma unroll
            for (int i = 0; i < 4; i++)
                #pragma unroll
                for (int j = 0; j < 4; j++)
                    #pragma unroll
                    for (int r = 0; r < 4; r++) c[i][j][r] = 0.0f;

            for (int kt = 0; kt < nch; kt++) {
                MBAR_WAIT(sb + cs * 8, cph);
                const uint32_t st = tile0 + (uint32_t)cs * STAGE;

                #pragma unroll
                for (int ks = 0; ks < 4; ks++) {
                    uint32_t bfrag[2][4], afrag[4][4];
                    #pragma unroll
                    for (int nb = 0; nb < 2; nb++)
                        ldsm4(st + addrB[ks][nb], bfrag[nb]);
                    #pragma unroll
                    for (int mb = 0; mb < 4; mb++)
                        ldsm4(st + addrA[ks][mb], afrag[mb]);
                    #pragma unroll
                    for (int mb = 0; mb < 4; mb++)
                        #pragma unroll
                        for (int n8 = 0; n8 < 4; n8++) {
                            const int nb = n8 >> 1, hf = n8 & 1;
                            mma16816(c[mb][n8], afrag[mb],
                                     bfrag[nb][hf], bfrag[nb][hf + 2]);
                        }
                }
                if (lane == 0) MBAR_ARRIVE(sb + 64 + cs * 8);
                if (tid == 0) issue();
                if (++cs == NSTAGE) { cs = 0; cph ^= 1; }
            }

            // ------- epilogue: mixg (+)= geno * act(c + bias) -------
            const float wgt = __ldg(&geno[layer * 5 + op]);
            __syncthreads();
            if (tid < 128)
                sbias[tid] = __ldg(&bsv[((size_t)layer * 5 + op) * 1024 + bn + tid]);
            __syncthreads();

            const bool first = (e == 0) && (op == 0);
            const bool last  = (e == P.n_edges - 1) && (op == 4);

            #define MIX_BODY(AEXPR)                                            \
                _Pragma("unroll")                                              \
                for (int mb = 0; mb < 4; mb++)                                 \
                _Pragma("unroll")                                              \
                for (int n8 = 0; n8 < 4; n8++)                                 \
                _Pragma("unroll")                                              \
                for (int r = 0; r < 4; r++) {                                  \
                    const float h = c[mb][n8][r] +                             \
                        sbias[nbase + n8 * 8 + (lane & 3) * 2 + (r & 1)];      \
                    const float v = wgt * (AEXPR);                             \
                    const int idx = ((mb * 4 + n8) * 4 + r) * 256 + tid;       \
                    if (first) mixg[idx] = v;                                  \
                    else if (!last) mixg[idx] += v;                            \
                    else {                                                     \
                        const float tot = mixg[idx] + v;                       \
                        const int m = bm + mbase + mb * 16 + (lane >> 2)       \
                                      + ((r >> 1) & 1) * 8;                    \
                        const int n = bn + nbase + n8 * 8 + (lane & 3) * 2     \
                                      + (r & 1);                               \
                        if (P.node_out_idx >= 0)                               \
                            g_x[P.node_out_idx][(size_t)m * 1024 + n] =        \
                                __float2half(tot);                             \
                        else                                                   \
                            outp[(size_t)m * 1024 + n] = tot;                  \
                    }                                                          \
                }
            switch (op) {
                case 0: MIX_BODY(h); break;
                case 1: MIX_BODY(fmaxf(h, 0.0f)); break;
                case 2: MIX_BODY(tanh_fast(h)); break;
                case 3: MIX_BODY(fmaf(tanh_fast(0.5f * h), 0.5f, 0.5f)); break;
                default: MIX_BODY(h > 0.0f ? h : 0.2f * h); break;
            }
            #undef MIX_BODY
        }
    }
}

// --------------------------------- host -------------------------------------
typedef CUresult (*EncodeFn)(CUtensorMap*, CUtensorMapDataType, cuuint32_t, void*,
                             const cuuint64_t*, const cuuint64_t*, const cuuint32_t*,
                             const cuuint32_t*, CUtensorMapInterleave, CUtensorMapSwizzle,
                             CUtensorMapL2promotion, CUtensorMapFloatOOBfill);

static void make2d(EncodeFn enc, CUtensorMap* out, void* base,
                   uint64_t dim0, uint64_t dim1, uint64_t stride_b, uint32_t boxh) {
    cuuint64_t dims[2]    = {dim0, dim1};
    cuuint64_t strides[1] = {stride_b};
    cuuint32_t box[2]     = {64u, boxh};
    cuuint32_t es[2]      = {1u, 1u};
    enc(out, CU_TENSOR_MAP_DATA_TYPE_FLOAT16, 2, base, dims, strides, box, es,
        CU_TENSOR_MAP_INTERLEAVE_NONE, CU_TENSOR_MAP_SWIZZLE_128B,
        CU_TENSOR_MAP_L2_PROMOTION_L2_128B, CU_TENSOR_MAP_FLOAT_OOB_FILL_NONE);
}

extern "C" void kernel_launch(void* const* d_in, const int* in_sizes, int n_in,
                              void* d_out, int out_size)
{
    const float *s0 = nullptr, *s1 = nullptr, *geno = nullptr;
    const float *Ws = nullptr, *Wb = nullptr, *bsv = nullptr;
    for (int i = 0; i < n_in; i++) {
        const long sz = (long)in_sizes[i];
        const float* p = (const float*)d_in[i];
        if      (sz == (long)BATCH * DDIM)   { if (!s0) s0 = p; else s1 = p; }
        else if (sz == 90L)                    geno = p;
        else if (sz == 73400320L)              Ws = p;
        else if (sz == 41943040L)              Wb = p;
        else if (sz == 92160L)                 bsv = p;
    }

    void *ws, *wb, *x;
    cudaGetSymbolAddress(&ws, g_ws);
    cudaGetSymbolAddress(&wb, g_wb);
    cudaGetSymbolAddress(&x,  g_x);

    void* fp = nullptr;
    cudaDriverEntryPointQueryResult qres;
    cudaGetDriverEntryPointByVersion("cuTensorMapEncodeTiled", &fp, 12000,
                                     cudaEnableDefault, &qres);
    EncodeFn enc = (EncodeFn)fp;

    NodeP base;
    for (int i = 0; i < 5; i++)
        make2d(enc, &base.a_map[i], (char*)x + (size_t)i * 4194304 * 2, 1024, 4096, 2048, 128);
    make2d(enc, &base.ws_map, ws, 1024, 71680, 2048, 128);
    make2d(enc, &base.wb_map, wb, 2048, 20480, 4096, 128);

    cvt_in2<<<4096, 256>>>(s0, s1);
    dim3 tb(32, 8);
    cvt_w2<<<dim3(64, 32, 90), tb>>>(Ws, Wb);

    cudaFuncSetAttribute(gemm_node, cudaFuncAttributeMaxDynamicSharedMemorySize, DYN_SMEM);

    dim3 grid(8, 32), blk(256);
    int si = 0, bi = 0, offset = 0;
    for (int node = 0; node < 4; node++) {
        NodeP P = base;
        P.n_edges = node + 3;
        for (int j = 0; j < node + 3; j++) {
            EdgeInfo& e = P.e[j];
            e.layer = offset + j;
            if (j == 2) {
                e.b_is_wb = 1; e.b_row_base = bi * 5 * 1024; bi++;
                e.K = 2048; e.a0 = 0; e.a1 = 1;
            } else {
                e.b_is_wb = 0; e.b_row_base = si * 5 * 1024; si++;
                e.K = 1024;
                e.a0 = e.a1 = (j < 2) ? j : (j - 1);
            }
        }
        P.node_out_idx = (node < 3) ? (2 + node) : -1;
        gemm_node<<<grid, blk, DYN_SMEM>>>(P, geno, bsv, (float*)d_out);
        offset += node + 3;
    }
}